// round 3
// baseline (speedup 1.0000x reference)
#include <cuda_runtime.h>

// ---------------- problem constants ----------------
#define BTOT  16384
#define LROWS 129          // y history length per batch
#define PP    32           // observation dim
#define MCC   16           // control dim
#define HH    24
#define MM    64
#define DTOT  128          // delays actually used: 0..127
#define NV    (127 * 576)  // V[n, i*24+l]

// ---------------- device scratch (static, no allocation) ----------------
__device__ __align__(16) float g_V[NV];
// combined weights, packed layout: [d][k=c/2][p][2]  (pairs over channel c)
__device__ __align__(16) float g_W[DTOT * 512];

// ---------------- f32x2 packed helpers ----------------
static __device__ __forceinline__ unsigned long long f32x2_fma(
    unsigned long long a, unsigned long long b, unsigned long long c) {
    unsigned long long d;
    asm("fma.rn.f32x2 %0, %1, %2, %3;" : "=l"(d) : "l"(a), "l"(b), "l"(c));
    return d;
}
static __device__ __forceinline__ unsigned long long f32x2_add(
    unsigned long long a, unsigned long long b) {
    unsigned long long d;
    asm("add.rn.f32x2 %0, %1, %2;" : "=l"(d) : "l"(a), "l"(b));
    return d;
}
static __device__ __forceinline__ unsigned long long pack_dup(float x) {
    unsigned long long d;
    asm("mov.b64 %0, {%1, %1};" : "=l"(d) : "f"(x));
    return d;
}
static __device__ __forceinline__ float2 unpack2(unsigned long long v) {
    float2 f;
    asm("mov.b64 {%0, %1}, %2;" : "=f"(f.x), "=f"(f.y) : "l"(v));
    return f;
}

// =====================================================================
// Kernel 1: V[n,i,l] = sum_{a+b=n} pt[a,i]*ps[b,l]   (full 1-D conv)
//           pt = phi_tilde * lambda^{1/4},  ps = phi * sigma^{1/4}
//           Also zeroes g_W (it is accumulated atomically by kernel 2).
// =====================================================================
__global__ __launch_bounds__(256) void pre_v_kernel(
    const float* __restrict__ sigma, const float* __restrict__ lambda,
    const float* __restrict__ phi,   const float* __restrict__ phit) {
    __shared__ float s_pt[MM * HH];  // [a][i]
    __shared__ float s_ps[MM * HH];  // [b][l]
    const int tid = threadIdx.x;
    for (int i = tid; i < MM * HH; i += 256) {
        const int col = i % HH;
        s_pt[i] = phit[i] * sqrtf(sqrtf(lambda[col]));
        s_ps[i] = phi[i]  * sqrtf(sqrtf(sigma[col]));
    }
    __syncthreads();

    const int idx = blockIdx.x * 256 + tid;
    if (idx < DTOT * 512) g_W[idx] = 0.0f;  // zero W for atomic accumulation

    if (idx < NV) {
        const int n = idx / 576;
        const int r = idx - n * 576;
        const int i = r / HH;
        const int l = r - i * HH;
        const int a0 = (n > 63) ? (n - 63) : 0;
        const int a1 = (n < 63) ? n : 63;
        float acc = 0.0f;
        for (int a = a0; a <= a1; ++a)
            acc += s_pt[a * HH + i] * s_ps[(n - a) * HH + l];
        g_V[idx] = acc;
    }
}

// =====================================================================
// Kernel 2: assemble combined W[d,c,p] (packed over channel pairs).
//   grid = (32 d-groups of 4, 4 il-chunks of 144), block = 512 (c,p)
//   term4:  W[d] += sum_il V[d-1,il] * M_big[il,c,p]
//   terms 1-3 added by the il-chunk-0 blocks.
// =====================================================================
__global__ __launch_bounds__(512) void pre_w_kernel(
    const float* __restrict__ M0,  const float* __restrict__ Mt,
    const float* __restrict__ M0l, const float* __restrict__ Mb,
    const float* __restrict__ sigma, const float* __restrict__ lambda,
    const float* __restrict__ phi,   const float* __restrict__ phit) {
    __shared__ float sV[4][144];
    __shared__ float s_l4[HH], s_s4[HH];
    const int tid = threadIdx.x;
    const int gx = blockIdx.x;   // d group: d = gx*4 + dd
    const int gy = blockIdx.y;   // il chunk: il in [gy*144, gy*144+144)

    if (tid < HH) {
        s_l4[tid] = sqrtf(sqrtf(lambda[tid]));
        s_s4[tid] = sqrtf(sqrtf(sigma[tid]));
    }
    for (int i = tid; i < 4 * 144; i += 512) {
        const int dd = i / 144;
        const int jj = i - dd * 144;
        const int n = gx * 4 + dd - 1;  // delay d -> conv index n = d-1
        sV[dd][jj] = (n >= 0) ? g_V[n * 576 + gy * 144 + jj] : 0.0f;
    }
    __syncthreads();

    float acc[4] = {0.f, 0.f, 0.f, 0.f};
    const float* mb = Mb + (size_t)(gy * 144) * 512 + tid;
#pragma unroll 4
    for (int j = 0; j < 144; ++j) {
        const float m = mb[(size_t)j * 512];
        acc[0] += sV[0][j] * m;
        acc[1] += sV[1][j] * m;
        acc[2] += sV[2][j] * m;
        acc[3] += sV[3][j] * m;
    }

    if (gy == 0) {
#pragma unroll
        for (int dd = 0; dd < 4; ++dd) {
            const int d = gx * 4 + dd;
            float a = acc[dd];
            if (d == 0) a += M0[tid];                       // term 1
            if (d >= 1 && d <= MM) {                        // term 2 (j = d)
                const int r = d - 1;
#pragma unroll 4
                for (int i = 0; i < HH; ++i)
                    a += phit[r * HH + i] * s_l4[i] * Mt[i * 512 + tid];
            }
            if (d <= MM - 1) {                              // term 3 (k = d)
#pragma unroll 4
                for (int l = 0; l < HH; ++l)
                    a += phi[d * HH + l] * s_s4[l] * M0l[l * 512 + tid];
            }
            acc[dd] = a;
        }
    }

    const int c = tid >> 5, p = tid & 31;
    const int base = (c >> 1) * 64 + p * 2 + (c & 1);   // packed-pair layout
#pragma unroll
    for (int dd = 0; dd < 4; ++dd)
        atomicAdd(&g_W[(gx * 4 + dd) * 512 + base], acc[dd]);
}

// =====================================================================
// Kernel 3 (main): u[b,c] = sum_{d,p} W[d,c,p] * y[b,d,p]
//   512 threads = 16 warps; each warp handles 4 batches, lane = p.
//   W staged in shared in 4 chunks of 32 delays (64 KB, packed c-pairs),
//   inner FMAs use packed fma.rn.f32x2 over channel pairs.
// =====================================================================
__global__ __launch_bounds__(512, 1) void main_kernel(
    const float* __restrict__ y, float* __restrict__ out) {
    extern __shared__ unsigned long long sW[];  // [32 d][8 k][32 p] = 64 KB
    const int tid  = threadIdx.x;
    const int lane = tid & 31;          // = p
    const int warp = tid >> 5;
    const int b0 = blockIdx.x * 64 + warp * 4;
    const float* y0 = y + (size_t)b0 * (LROWS * PP) + lane;

    unsigned long long acc[4][8];
#pragma unroll
    for (int j = 0; j < 4; ++j)
#pragma unroll
        for (int k = 0; k < 8; ++k) acc[j][k] = 0ull;

    for (int ch = 0; ch < 4; ++ch) {
        __syncthreads();
        // stage 64 KB W chunk (straight copy, layout already packed)
        const float4* src = reinterpret_cast<const float4*>(g_W) + ch * 4096;
        float4* dst = reinterpret_cast<float4*>(sW);
#pragma unroll
        for (int i = 0; i < 8; ++i) dst[tid + i * 512] = src[tid + i * 512];
        __syncthreads();

#pragma unroll 2
        for (int dq = 0; dq < 8; ++dq) {        // 4 delays per dq
            const int dbase = ch * 32 + dq * 4;
            float yv[4][4];
#pragma unroll
            for (int t = 0; t < 4; ++t)
#pragma unroll
                for (int j = 0; j < 4; ++j)
                    yv[t][j] = y0[(size_t)j * (LROWS * PP) + (dbase + t) * PP];
#pragma unroll
            for (int t = 0; t < 4; ++t) {
                unsigned long long y2[4];
#pragma unroll
                for (int j = 0; j < 4; ++j) y2[j] = pack_dup(yv[t][j]);
#pragma unroll
                for (int k = 0; k < 8; ++k) {
                    const unsigned long long w2 =
                        sW[((dq * 4 + t) * 8 + k) * 32 + lane];
#pragma unroll
                    for (int j = 0; j < 4; ++j)
                        acc[j][k] = f32x2_fma(y2[j], w2, acc[j][k]);
                }
            }
        }
    }

    // butterfly reduce over p (lanes); packed add keeps pairs intact
#pragma unroll
    for (int j = 0; j < 4; ++j)
#pragma unroll
        for (int k = 0; k < 8; ++k) {
            unsigned long long v = acc[j][k];
#pragma unroll
            for (int off = 16; off > 0; off >>= 1)
                v = f32x2_add(v, __shfl_xor_sync(0xffffffffu, v, off));
            acc[j][k] = v;
        }

    if (lane < MCC) {
        const int k = lane >> 1;
        const bool hi = lane & 1;
#pragma unroll
        for (int j = 0; j < 4; ++j) {
            const float2 f = unpack2(acc[j][k]);
            out[(size_t)(b0 + j) * MCC + lane] = hi ? f.y : f.x;
        }
    }
}

// =====================================================================
extern "C" void kernel_launch(void* const* d_in, const int* in_sizes, int n_in,
                              void* d_out, int out_size) {
    const float* y      = (const float*)d_in[0];  // [16384,129,32]
    const float* M0     = (const float*)d_in[1];  // [16,32]
    const float* Mt     = (const float*)d_in[2];  // [24,16,32]
    const float* M0l    = (const float*)d_in[3];  // [24,16,32]
    const float* Mb     = (const float*)d_in[4];  // [24,24,16,32]
    const float* sigma  = (const float*)d_in[5];  // [24]
    const float* lambda = (const float*)d_in[6];  // [24]
    const float* phi    = (const float*)d_in[7];  // [64,24]
    const float* phit   = (const float*)d_in[8];  // [64,24]
    float* out = (float*)d_out;                   // [16384,16]

    pre_v_kernel<<<(NV + 255) / 256, 256>>>(sigma, lambda, phi, phit);

    dim3 gw(32, 4);
    pre_w_kernel<<<gw, 512>>>(M0, Mt, M0l, Mb, sigma, lambda, phi, phit);

    cudaFuncSetAttribute(main_kernel,
                         cudaFuncAttributeMaxDynamicSharedMemorySize, 65536);
    main_kernel<<<BTOT / 64, 512, 65536>>>(y, out);
}

// round 4
// speedup vs baseline: 1.2026x; 1.2026x over previous
#include <cuda_runtime.h>
#include <cstdint>

// ---------------- problem constants ----------------
#define BTOT  16384
#define LROWS 129          // y history length per batch (only d=0..127 used)
#define PP    32           // observation dim
#define MCC   16           // control dim
#define HH    24
#define MM    64
#define DTOT  128
#define YROW  (LROWS * PP)     // 4128 floats per batch
typedef unsigned long long ull;

// combined weights, packed layout: [d][k=c/2][p] as f32x2 pairs (512 floats/d)
__device__ __align__(16) float g_W[DTOT * 512];

// ---------------- f32x2 packed helpers ----------------
static __device__ __forceinline__ ull f32x2_fma(ull a, ull b, ull c) {
    ull d;
    asm("fma.rn.f32x2 %0, %1, %2, %3;" : "=l"(d) : "l"(a), "l"(b), "l"(c));
    return d;
}
static __device__ __forceinline__ ull f32x2_add(ull a, ull b) {
    ull d;
    asm("add.rn.f32x2 %0, %1, %2;" : "=l"(d) : "l"(a), "l"(b));
    return d;
}
static __device__ __forceinline__ ull pack_dup(float x) {
    ull d;
    asm("mov.b64 %0, {%1, %1};" : "=l"(d) : "f"(x));
    return d;
}
static __device__ __forceinline__ float2 unpack2(ull v) {
    float2 f;
    asm("mov.b64 {%0, %1}, %2;" : "=f"(f.x), "=f"(f.y) : "l"(v));
    return f;
}

// ---------------- smem / mbarrier / bulk-copy helpers ----------------
static __device__ __forceinline__ uint32_t smem_u32(const void* p) {
    return (uint32_t)__cvta_generic_to_shared(p);
}
static __device__ __forceinline__ void mbar_init(uint32_t addr, uint32_t cnt) {
    asm volatile("mbarrier.init.shared.b64 [%0], %1;" :: "r"(addr), "r"(cnt) : "memory");
}
static __device__ __forceinline__ void mbar_expect_tx(uint32_t addr, uint32_t bytes) {
    asm volatile("mbarrier.arrive.expect_tx.shared.b64 _, [%0], %1;"
                 :: "r"(addr), "r"(bytes) : "memory");
}
static __device__ __forceinline__ void mbar_wait(uint32_t addr, uint32_t phase) {
    uint32_t done;
    asm volatile(
        "{\n\t.reg .pred p;\n\t"
        "mbarrier.try_wait.parity.acquire.cta.shared::cta.b64 p, [%1], %2;\n\t"
        "selp.b32 %0, 1, 0, p;\n\t}"
        : "=r"(done) : "r"(addr), "r"(phase) : "memory");
    if (!done) {
        asm volatile(
            "{\n\t.reg .pred P1;\n\t"
            "WL_%=:\n\t"
            "mbarrier.try_wait.parity.acquire.cta.shared::cta.b64 P1, [%0], %1, 0x989680;\n\t"
            "@P1 bra.uni WD_%=;\n\t"
            "bra.uni WL_%=;\n\t"
            "WD_%=:\n\t}"
            :: "r"(addr), "r"(phase) : "memory");
    }
}
static __device__ __forceinline__ void bulk_copy_g2s(uint32_t dst_smem,
                                                     const void* src_gmem,
                                                     uint32_t bytes,
                                                     uint32_t mbar_addr) {
    asm volatile(
        "cp.async.bulk.shared::cta.global.mbarrier::complete_tx::bytes "
        "[%0], [%1], %2, [%3];"
        :: "r"(dst_smem), "l"(src_gmem), "r"(bytes), "r"(mbar_addr) : "memory");
}

// =====================================================================
// Pre kernel (fused): builds combined W[d,c,p] (channel-pair packed).
//   grid = (32 d-groups of 4, 4 il-chunks of 144), block = 512 threads.
//   V[n, il] (conv of scaled phi_tilde and phi) is computed inline in smem.
//   g_W must be zeroed beforehand (cudaMemsetAsync); partials accumulate
//   via atomicAdd (4-way contention per address, negligible).
// =====================================================================
__global__ __launch_bounds__(512) void pre_kernel(
    const float* __restrict__ M0,  const float* __restrict__ Mt,
    const float* __restrict__ M0l, const float* __restrict__ Mb,
    const float* __restrict__ sigma, const float* __restrict__ lambda,
    const float* __restrict__ phi,   const float* __restrict__ phit) {
    __shared__ float s_pt[MM * HH];   // [a][i] phi_tilde * lambda^{1/4}
    __shared__ float s_ps[MM * HH];   // [b][l] phi       * sigma^{1/4}
    __shared__ float sV[4][144];
    __shared__ float s_l4[HH], s_s4[HH];
    const int tid = threadIdx.x;
    const int gx = blockIdx.x;   // d group: d = gx*4 + dd
    const int gy = blockIdx.y;   // il chunk: il in [gy*144, gy*144+144)

    if (tid < HH) {
        s_l4[tid] = sqrtf(sqrtf(lambda[tid]));
        s_s4[tid] = sqrtf(sqrtf(sigma[tid]));
    }
    __syncthreads();
    for (int i = tid; i < MM * HH; i += 512) {
        const int col = i % HH;
        s_pt[i] = phit[i] * s_l4[col];
        s_ps[i] = phi[i]  * s_s4[col];
    }
    __syncthreads();

    // inline V: conv index n = d-1;  V[n,i,l] = sum_{a+b=n} pt[a,i] ps[b,l]
    for (int idx = tid; idx < 4 * 144; idx += 512) {
        const int dd = idx / 144;
        const int rr = idx - dd * 144;
        const int il = gy * 144 + rr;
        const int i  = il / HH;
        const int l  = il - i * HH;
        const int n  = gx * 4 + dd - 1;
        float acc = 0.0f;
        if (n >= 0) {
            const int a0 = (n > MM - 1) ? (n - (MM - 1)) : 0;
            const int a1 = (n < MM - 1) ? n : (MM - 1);
            for (int a = a0; a <= a1; ++a)
                acc += s_pt[a * HH + i] * s_ps[(n - a) * HH + l];
        }
        sV[dd][rr] = acc;
    }
    __syncthreads();

    float acc[4] = {0.f, 0.f, 0.f, 0.f};
    const float* mb = Mb + (size_t)(gy * 144) * 512 + tid;
#pragma unroll 4
    for (int j = 0; j < 144; ++j) {
        const float m = mb[(size_t)j * 512];
        acc[0] += sV[0][j] * m;
        acc[1] += sV[1][j] * m;
        acc[2] += sV[2][j] * m;
        acc[3] += sV[3][j] * m;
    }

    if (gy == 0) {   // terms 1-3, each delay handled exactly once
#pragma unroll
        for (int dd = 0; dd < 4; ++dd) {
            const int d = gx * 4 + dd;
            float a = acc[dd];
            if (d == 0) a += M0[tid];                       // term 1
            if (d >= 1 && d <= MM) {                        // term 2 (j = d)
                const int r = d - 1;
#pragma unroll 4
                for (int i = 0; i < HH; ++i)
                    a += phit[r * HH + i] * s_l4[i] * Mt[i * 512 + tid];
            }
            if (d <= MM - 1) {                              // term 3 (k = d)
#pragma unroll 4
                for (int l = 0; l < HH; ++l)
                    a += phi[d * HH + l] * s_s4[l] * M0l[l * 512 + tid];
            }
            acc[dd] = a;
        }
    }

    const int c = tid >> 5, p = tid & 31;
    const int base = (c >> 1) * 64 + p * 2 + (c & 1);   // packed-pair layout
#pragma unroll
    for (int dd = 0; dd < 4; ++dd)
        atomicAdd(&g_W[(gx * 4 + dd) * 512 + base], acc[dd]);
}

// =====================================================================
// Main kernel: u[b,c] = sum_{d,p} W[d,c,p] * y[b,d,p]
//   256 CTAs x 512 threads; warp = 4 batches, lane = p.
//   W streamed through double-buffered smem (2 x 64 KB) via cp.async.bulk
//   issued by one thread, overlapped with compute; y software-prefetched
//   one delay ahead; inner FMAs are packed fma.rn.f32x2 over channel pairs.
// =====================================================================
__global__ __launch_bounds__(512, 1) void main_kernel(
    const float* __restrict__ y, float* __restrict__ out) {
    extern __shared__ __align__(16) ull sbuf[];   // 2 x 8192 ull = 128 KB
    __shared__ __align__(8) ull mbar_store[2];

    const int tid  = threadIdx.x;
    const int lane = tid & 31;          // = p
    const int warp = tid >> 5;
    const uint32_t mb0 = smem_u32(&mbar_store[0]);
    const uint32_t mb1 = smem_u32(&mbar_store[1]);

    if (tid == 0) {
        mbar_init(mb0, 1);
        mbar_init(mb1, 1);
        asm volatile("fence.proxy.async.shared::cta;" ::: "memory");
    }
    __syncthreads();
    if (tid == 0) {
        mbar_expect_tx(mb0, 65536);
        bulk_copy_g2s(smem_u32(sbuf), g_W, 65536, mb0);
        mbar_expect_tx(mb1, 65536);
        bulk_copy_g2s(smem_u32(sbuf + 8192), g_W + 16384, 65536, mb1);
    }

    const int b0 = blockIdx.x * 64 + warp * 4;
    const float* __restrict__ yp = y + (size_t)b0 * YROW + lane;

    ull acc[4][8];
#pragma unroll
    for (int j = 0; j < 4; ++j)
#pragma unroll
        for (int k = 0; k < 8; ++k) acc[j][k] = 0ull;

    // prefetch y for d = 0
    float yn[4];
#pragma unroll
    for (int j = 0; j < 4; ++j) yn[j] = yp[(size_t)j * YROW];

    for (int ch = 0; ch < 4; ++ch) {
        mbar_wait((ch & 1) ? mb1 : mb0, ch >> 1);
        const ull* __restrict__ wb = sbuf + (ch & 1) * 8192;

#pragma unroll 4
        for (int dl = 0; dl < 32; ++dl) {
            const int d = ch * 32 + dl;
            ull y2[4];
#pragma unroll
            for (int j = 0; j < 4; ++j) y2[j] = pack_dup(yn[j]);
            // prefetch next delay (d+1 <= 128: row exists, LROWS = 129)
#pragma unroll
            for (int j = 0; j < 4; ++j)
                yn[j] = yp[(size_t)(d + 1) * PP + (size_t)j * YROW];

            const ull* wrow = wb + dl * 256 + lane;
#pragma unroll
            for (int k = 0; k < 8; ++k) {
                const ull w2 = wrow[k * 32];
#pragma unroll
                for (int j = 0; j < 4; ++j)
                    acc[j][k] = f32x2_fma(y2[j], w2, acc[j][k]);
            }
        }
        __syncthreads();   // all warps done reading this buffer
        if (ch < 2 && tid == 0) {
            const uint32_t mb = (ch & 1) ? mb1 : mb0;
            mbar_expect_tx(mb, 65536);
            bulk_copy_g2s(smem_u32(sbuf + (ch & 1) * 8192),
                          g_W + (ch + 2) * 16384, 65536, mb);
        }
    }

    // butterfly reduce over p (lanes); packed add keeps channel pairs intact
#pragma unroll
    for (int j = 0; j < 4; ++j)
#pragma unroll
        for (int k = 0; k < 8; ++k) {
            ull v = acc[j][k];
#pragma unroll
            for (int off = 16; off > 0; off >>= 1)
                v = f32x2_add(v, __shfl_xor_sync(0xffffffffu, v, off));
            acc[j][k] = v;
        }

    if (lane < MCC) {
        const int k = lane >> 1;
        const bool hi = lane & 1;
#pragma unroll
        for (int j = 0; j < 4; ++j) {
            const float2 f = unpack2(acc[j][k]);
            out[(size_t)(b0 + j) * MCC + lane] = hi ? f.y : f.x;
        }
    }
}

// =====================================================================
extern "C" void kernel_launch(void* const* d_in, const int* in_sizes, int n_in,
                              void* d_out, int out_size) {
    const float* y      = (const float*)d_in[0];  // [16384,129,32]
    const float* M0     = (const float*)d_in[1];  // [16,32]
    const float* Mt     = (const float*)d_in[2];  // [24,16,32]
    const float* M0l    = (const float*)d_in[3];  // [24,16,32]
    const float* Mb     = (const float*)d_in[4];  // [24,24,16,32]
    const float* sigma  = (const float*)d_in[5];  // [24]
    const float* lambda = (const float*)d_in[6];  // [24]
    const float* phi    = (const float*)d_in[7];  // [64,24]
    const float* phit   = (const float*)d_in[8];  // [64,24]
    float* out = (float*)d_out;                   // [16384,16]

    void* wptr = nullptr;
    cudaGetSymbolAddress(&wptr, g_W);
    cudaMemsetAsync(wptr, 0, (size_t)DTOT * 512 * sizeof(float), 0);

    dim3 gw(32, 4);
    pre_kernel<<<gw, 512>>>(M0, Mt, M0l, Mb, sigma, lambda, phi, phit);

    cudaFuncSetAttribute(main_kernel,
                         cudaFuncAttributeMaxDynamicSharedMemorySize, 131072);
    main_kernel<<<BTOT / 64, 512, 131072>>>(y, out);
}